// round 14
// baseline (speedup 1.0000x reference)
#include <cuda_runtime.h>
#include <cuda_bf16.h>
#include <cuda_fp16.h>
#include <cstdint>

#define Nn 100000
#define Ee 1600000
#define Hh 128
#define Gg 64
#define EPSf 1e-5f

#define SCAN_BS 1024
#define NBLK ((Nn + SCAN_BS - 1) / SCAN_BS)   // 98
#define BN_REP 4
#define TILES ((Nn + 127) / 128)              // 782
#define DINVB ((Nn + 127) / 128)              // 782

// ---------------- mma GEMM smem layout (128 rows per tile, 2 CTAs/SM) ----------------
#define Pp 136                        // bf16 elements per row (272 B)
#define AIMG_B (128 * Pp * 2)         // 34816 B (A hi only)
#define WIMG_B (128 * Pp * 2)         // 34816 B per W image
#define SM_AHI 0
#define SM_W   AIMG_B                 // W hi at +0, W lo at +WIMG_B
#define SM_BN  (AIMG_B + 2 * WIMG_B)  // 104448
#define SM_TOTAL (SM_BN + 1024)       // 105472 B -> 2 blocks/SM

#define MMA_BF16(d, a, b0, b1) \
    asm volatile("mma.sync.aligned.m16n8k16.row.col.f32.bf16.bf16.f32 " \
        "{%0,%1,%2,%3}, {%4,%5,%6,%7}, {%8,%9}, {%0,%1,%2,%3};" \
        : "+f"((d)[0]), "+f"((d)[1]), "+f"((d)[2]), "+f"((d)[3]) \
        : "r"((a)[0]), "r"((a)[1]), "r"((a)[2]), "r"((a)[3]), "r"(b0), "r"(b1))

// ---------------- device scratch ----------------
struct ZBlob {
    int   deg[Nn];
    int   cursor[Nn];
    float bnsum[3][BN_REP][2 * Hh];
    float xsum[Gg * Hh];
    float cnt[Gg];
};
__device__ ZBlob g_z;
__device__ float g_dinv[Nn];
__device__ int   g_off[Nn + 1];
__device__ int   g_bsum[SCAN_BS];
__device__ int   g_csr[Ee];                       // src only (weights folded into h')
__device__ __half g_h16[(size_t)Nn * Hh];         // h' = dinv * (A @ W), fp16
__device__ float g_agg[(size_t)Nn * Hh];
__device__ float g_act[(size_t)Nn * Hh];
__device__ __nv_bfloat16 g_wt[3][2][128 * Pp];    // padded W^T bf16 hi/lo images

// ---------------- degree ----------------
__global__ void k_deg(const int* __restrict__ dst) {
    int e = blockIdx.x * blockDim.x + threadIdx.x;
    if (e < Ee) atomicAdd(&g_z.deg[dst[e]], 1);
}

// ---- prep: dinv (blocks [0,DINVB)) + W split (blocks [DINVB, DINVB+384)) ----
__global__ void k_prep(const float* __restrict__ W1, const float* __restrict__ W2,
                       const float* __restrict__ W3) {
    int b = blockIdx.x;
    if (b < DINVB) {
        int i = b * 128 + threadIdx.x;
        if (i < Nn) g_dinv[i] = rsqrtf((float)g_z.deg[i] + 1.0f);
    } else {
        int bi = b - DINVB;                 // 0..383
        int layer = bi >> 7;
        int n = bi & 127;
        const float* Ws = (layer == 0) ? W1 : (layer == 1) ? W2 : W3;
        int k = threadIdx.x;
        float v = Ws[k * 128 + n];
        __nv_bfloat16 hi = __float2bfloat16(v);
        float lo = v - __bfloat162float(hi);
        g_wt[layer][0][n * Pp + k] = hi;
        g_wt[layer][1][n * Pp + k] = __float2bfloat16(lo);
    }
}

// ---------------- exclusive scan of degrees -> CSR offsets ----------------
__global__ void k_scan1() {
    __shared__ int s[SCAN_BS];
    int tid = threadIdx.x;
    int i = blockIdx.x * SCAN_BS + tid;
    int v = (i < Nn) ? g_z.deg[i] : 0;
    s[tid] = v;
    __syncthreads();
    for (int d = 1; d < SCAN_BS; d <<= 1) {
        int t = (tid >= d) ? s[tid - d] : 0;
        __syncthreads();
        s[tid] += t;
        __syncthreads();
    }
    if (i < Nn) g_off[i] = s[tid] - v;
    if (tid == SCAN_BS - 1) g_bsum[blockIdx.x] = s[tid];
}

__global__ void k_scan2() {
    __shared__ int s[128];
    int tid = threadIdx.x;
    int v = (tid < NBLK) ? g_bsum[tid] : 0;
    s[tid] = v;
    __syncthreads();
    for (int d = 1; d < 128; d <<= 1) {
        int t = (tid >= d) ? s[tid - d] : 0;
        __syncthreads();
        s[tid] += t;
        __syncthreads();
    }
    g_bsum[tid] = s[tid] - v;
}

__global__ void k_scan3() {
    int i = blockIdx.x * blockDim.x + threadIdx.x;
    if (i < Nn) g_off[i] += g_bsum[i >> 10];
    if (i == 0) g_off[Nn] = Ee;
}

__global__ void k_fill(const int* __restrict__ src, const int* __restrict__ dst) {
    int e = blockIdx.x * blockDim.x + threadIdx.x;
    if (e >= Ee) return;
    int d = dst[e];
    int pos = g_off[d] + atomicAdd(&g_z.cursor[d], 1);
    g_csr[pos] = src[e];
}

// ---- tensor GEMM: g_h16[M,128] = fp16( dinv * (bf16(A) @ W) ) ----
// 256 threads, 128 rows/tile, 2 CTAs/SM. Products: Ahi*Whi + Ahi*Wlo.
// mode 0: A = Ain; mode 1: A = relu(bn(g_agg)) -> also g_act;
// mode 2: A = relu(bn(g_agg)) + g_act -> also g_act
__global__ __launch_bounds__(256)
void gemm_tc(const float* __restrict__ Ain, int layer, int mode, int bnidx,
             const float* __restrict__ gam, const float* __restrict__ bet) {
    extern __shared__ char sm[];
    float* s_bn = (float*)(sm + SM_BN);
    int tid = threadIdx.x;
    int wid = tid >> 5;
    int lane = tid & 31;
    int gid = lane >> 2;
    int tig = lane & 3;
    int row0 = blockIdx.x * 128;

    // W hi+lo images -> smem (69632 B)
    {
        const uint4* wsrc = (const uint4*)(&g_wt[layer][0][0]);
        uint4* wdst = (uint4*)(sm + SM_W);
        for (int i = tid; i < 4352; i += 256) wdst[i] = wsrc[i];
    }
    // BN scale/shift
    if (mode && tid < 128) {
        float s = 0.f, q = 0.f;
#pragma unroll
        for (int r = 0; r < BN_REP; r++) {
            s += g_z.bnsum[bnidx][r][tid];
            q += g_z.bnsum[bnidx][r][128 + tid];
        }
        float mean = s * (1.0f / (float)Nn);
        float var = q * (1.0f / (float)Nn) - mean * mean;
        float sc = gam[tid] * rsqrtf(var + EPSf);
        s_bn[tid] = sc;
        s_bn[128 + tid] = bet[tid] - mean * sc;
    }
    __syncthreads();

    // A prologue: 256 threads cover 128 rows x 2 halves (hi image only)
    {
        int r = tid & 127;
        int half = tid >> 7;
        int gr = row0 + r;
#pragma unroll
        for (int j = 0; j < 8; j++) {
            int k0 = half * 64 + j * 8;
            float4 va = make_float4(0.f, 0.f, 0.f, 0.f), vb = va;
            if (gr < Nn) {
                if (mode == 0) {
                    const float4* ap = (const float4*)(Ain + (size_t)gr * 128 + k0);
                    va = ap[0]; vb = ap[1];
                } else {
                    const float4* ap = (const float4*)(g_agg + (size_t)gr * 128 + k0);
                    float4 a0 = ap[0], a1 = ap[1];
                    const float4* scp = (const float4*)(s_bn + k0);
                    const float4* shp = (const float4*)(s_bn + 128 + k0);
                    float4 s0 = scp[0], s1 = scp[1], h0 = shp[0], h1 = shp[1];
                    va.x = fmaxf(fmaf(a0.x, s0.x, h0.x), 0.f);
                    va.y = fmaxf(fmaf(a0.y, s0.y, h0.y), 0.f);
                    va.z = fmaxf(fmaf(a0.z, s0.z, h0.z), 0.f);
                    va.w = fmaxf(fmaf(a0.w, s0.w, h0.w), 0.f);
                    vb.x = fmaxf(fmaf(a1.x, s1.x, h1.x), 0.f);
                    vb.y = fmaxf(fmaf(a1.y, s1.y, h1.y), 0.f);
                    vb.z = fmaxf(fmaf(a1.z, s1.z, h1.z), 0.f);
                    vb.w = fmaxf(fmaf(a1.w, s1.w, h1.w), 0.f);
                    if (mode == 2) {
                        const float4* rp = (const float4*)(g_act + (size_t)gr * 128 + k0);
                        float4 r0 = rp[0], r1 = rp[1];
                        va.x += r0.x; va.y += r0.y; va.z += r0.z; va.w += r0.w;
                        vb.x += r1.x; vb.y += r1.y; vb.z += r1.z; vb.w += r1.w;
                    }
                    float4* op = (float4*)(g_act + (size_t)gr * 128 + k0);
                    op[0] = va; op[1] = vb;
                }
            }
            float vv[8] = {va.x, va.y, va.z, va.w, vb.x, vb.y, vb.z, vb.w};
            uint32_t hw[4];
#pragma unroll
            for (int q = 0; q < 4; q++) {
                __nv_bfloat162 hb = __floats2bfloat162_rn(vv[2 * q], vv[2 * q + 1]);
                hw[q] = *(uint32_t*)&hb;
            }
            size_t off = ((size_t)r * Pp + k0) * 2;
            *(uint4*)(sm + SM_AHI + off) = make_uint4(hw[0], hw[1], hw[2], hw[3]);
        }
    }
    __syncthreads();

    // main loop: 8 warps, warp tile 32 rows x 64 cols
    int m0 = (wid >> 1) * 32;
    int nb = (wid & 1) * 64;

    float acc[2][8][4];
#pragma unroll
    for (int t = 0; t < 2; t++)
#pragma unroll
        for (int nt = 0; nt < 8; nt++) {
            acc[t][nt][0] = 0.f; acc[t][nt][1] = 0.f;
            acc[t][nt][2] = 0.f; acc[t][nt][3] = 0.f;
        }

#pragma unroll 1
    for (int kc = 0; kc < 8; kc++) {
        int k0 = kc * 16;
        uint32_t ah[2][4];
#pragma unroll
        for (int t = 0; t < 2; t++) {
            size_t o0 = ((size_t)(m0 + t * 16 + gid) * Pp + k0 + tig * 2) * 2;
            size_t o1 = ((size_t)(m0 + t * 16 + 8 + gid) * Pp + k0 + tig * 2) * 2;
            ah[t][0] = *(const uint32_t*)(sm + SM_AHI + o0);
            ah[t][1] = *(const uint32_t*)(sm + SM_AHI + o1);
            ah[t][2] = *(const uint32_t*)(sm + SM_AHI + o0 + 16);
            ah[t][3] = *(const uint32_t*)(sm + SM_AHI + o1 + 16);
        }
#pragma unroll
        for (int nt = 0; nt < 8; nt++) {
            size_t bo = ((size_t)(nb + nt * 8 + gid) * Pp + k0 + tig * 2) * 2;
            uint32_t bh0 = *(const uint32_t*)(sm + SM_W + bo);
            uint32_t bh1 = *(const uint32_t*)(sm + SM_W + bo + 16);
            uint32_t bl0 = *(const uint32_t*)(sm + SM_W + WIMG_B + bo);
            uint32_t bl1 = *(const uint32_t*)(sm + SM_W + WIMG_B + bo + 16);
#pragma unroll
            for (int t = 0; t < 2; t++) {
                MMA_BF16(acc[t][nt], ah[t], bh0, bh1);
                MMA_BF16(acc[t][nt], ah[t], bl0, bl1);
            }
        }
    }

    // epilogue: scale by dinv, convert to fp16
#pragma unroll
    for (int t = 0; t < 2; t++) {
        int r1 = row0 + m0 + t * 16 + gid;
        int r2 = r1 + 8;
        float dv1 = (r1 < Nn) ? g_dinv[r1] : 0.f;
        float dv2 = (r2 < Nn) ? g_dinv[r2] : 0.f;
#pragma unroll
        for (int nt = 0; nt < 8; nt++) {
            int c2 = (wid & 1) * 32 + nt * 4 + tig;
            if (r1 < Nn) {
                __half2 p = __floats2half2_rn(acc[t][nt][0] * dv1, acc[t][nt][1] * dv1);
                ((uint32_t*)g_h16)[(size_t)r1 * 64 + c2] = *(uint32_t*)&p;
            }
            if (r2 < Nn) {
                __half2 p = __floats2half2_rn(acc[t][nt][2] * dv2, acc[t][nt][3] * dv2);
                ((uint32_t*)g_h16)[(size_t)r2 * 64 + c2] = *(uint32_t*)&p;
            }
        }
    }
}

// ------- gather: warp-staged CSR (coalesced) + shfl broadcast, 4-deep rows -------
// agg[d] = dinv[d] * (h'[d] + sum_e h'[src_e]) + bias
__global__ __launch_bounds__(512) void k_gather(const float* __restrict__ bias, int bnidx) {
    __shared__ float ss[16 * 128];

    int tid = threadIdx.x;
    int wloc = tid >> 5;
    int lane = tid & 31;
    int wid = blockIdx.x * 16 + wloc;

    int beg = g_off[wid];
    int end = g_off[wid + 1];
    float dn = g_dinv[wid];

    const uint2* hv = (const uint2*)g_h16;
    uint2 hs = hv[(size_t)wid * 32 + lane];
    float2 f0 = __half22float2(*(__half2*)&hs.x);
    float2 f1 = __half22float2(*(__half2*)&hs.y);
    float4 acc = make_float4(f0.x, f0.y, f1.x, f1.y);
    float4 acc2 = make_float4(0.f, 0.f, 0.f, 0.f);

    const int* csr = g_csr;
    int e = beg;
    while (e < end) {
        int cnt = end - e;
        if (cnt > 32) cnt = 32;
        int myidx = (lane < cnt) ? csr[e + lane] : 0;
        int j = 0;
        for (; j + 4 <= cnt; j += 4) {
            int s0 = __shfl_sync(0xffffffffu, myidx, j);
            int s1 = __shfl_sync(0xffffffffu, myidx, j + 1);
            int s2 = __shfl_sync(0xffffffffu, myidx, j + 2);
            int s3 = __shfl_sync(0xffffffffu, myidx, j + 3);
            uint2 v0 = hv[(size_t)s0 * 32 + lane];
            uint2 v1 = hv[(size_t)s1 * 32 + lane];
            uint2 v2 = hv[(size_t)s2 * 32 + lane];
            uint2 v3 = hv[(size_t)s3 * 32 + lane];
            float2 a0 = __half22float2(*(__half2*)&v0.x), a1 = __half22float2(*(__half2*)&v0.y);
            float2 b0 = __half22float2(*(__half2*)&v1.x), b1 = __half22float2(*(__half2*)&v1.y);
            float2 d0 = __half22float2(*(__half2*)&v2.x), d1 = __half22float2(*(__half2*)&v2.y);
            float2 e0 = __half22float2(*(__half2*)&v3.x), e1 = __half22float2(*(__half2*)&v3.y);
            acc.x += a0.x + d0.x;  acc.y += a0.y + d0.y;
            acc.z += a1.x + d1.x;  acc.w += a1.y + d1.y;
            acc2.x += b0.x + e0.x; acc2.y += b0.y + e0.y;
            acc2.z += b1.x + e1.x; acc2.w += b1.y + e1.y;
        }
        for (; j < cnt; j++) {
            int s0 = __shfl_sync(0xffffffffu, myidx, j);
            uint2 v0 = hv[(size_t)s0 * 32 + lane];
            float2 a0 = __half22float2(*(__half2*)&v0.x);
            float2 a1 = __half22float2(*(__half2*)&v0.y);
            acc.x += a0.x; acc.y += a0.y; acc.z += a1.x; acc.w += a1.y;
        }
        e += cnt;
    }
    acc.x += acc2.x; acc.y += acc2.y; acc.z += acc2.z; acc.w += acc2.w;

    float4 b4 = ((const float4*)bias)[lane];
    acc.x = fmaf(acc.x, dn, b4.x);
    acc.y = fmaf(acc.y, dn, b4.y);
    acc.z = fmaf(acc.z, dn, b4.z);
    acc.w = fmaf(acc.w, dn, b4.w);
    ((float4*)g_agg)[(size_t)wid * 32 + lane] = acc;

    int base = wloc * 128 + lane * 4;
    ss[base + 0] = acc.x; ss[base + 1] = acc.y; ss[base + 2] = acc.z; ss[base + 3] = acc.w;
    __syncthreads();

    if (tid < 256) {
        int c = tid & 127;
        int part = tid >> 7;
        float r = 0.f;
        if (part == 0) {
#pragma unroll
            for (int w = 0; w < 16; w++) r += ss[w * 128 + c];
        } else {
#pragma unroll
            for (int w = 0; w < 16; w++) { float v = ss[w * 128 + c]; r = fmaf(v, v, r); }
        }
        atomicAdd(&g_z.bnsum[bnidx][blockIdx.x & (BN_REP - 1)][part * 128 + c], r);
    }
}

// ---------------- pooling with fused layer-3 BN finalize+apply ----------------
#define PCHUNK 128
__global__ void k_pool(const int* __restrict__ batch,
                       const float* __restrict__ gam, const float* __restrict__ bet) {
    int c = threadIdx.x;
    float s = 0.f, q = 0.f;
#pragma unroll
    for (int r = 0; r < BN_REP; r++) {
        s += g_z.bnsum[2][r][c];
        q += g_z.bnsum[2][r][128 + c];
    }
    float mean = s * (1.0f / (float)Nn);
    float var = q * (1.0f / (float)Nn) - mean * mean;
    float sc = gam[c] * rsqrtf(var + EPSf);
    float sh = bet[c] - mean * sc;

    int start = blockIdx.x * PCHUNK;
    if (start >= Nn) return;
    int end = min(start + PCHUNK, Nn);
    float acc = 0.f, ccnt = 0.f;
    int gp = batch[start];
    for (int n = start; n < end; n++) {
        int g = batch[n];
        if (g != gp) {
            atomicAdd(&g_z.xsum[gp * 128 + c], acc);
            if (c == 0) atomicAdd(&g_z.cnt[gp], ccnt);
            acc = 0.f; ccnt = 0.f; gp = g;
        }
        float a = g_agg[(size_t)n * 128 + c];
        float v = fmaxf(fmaf(a, sc, sh), 0.f) + g_act[(size_t)n * 128 + c];
        acc += v;
        ccnt += 1.f;
    }
    atomicAdd(&g_z.xsum[gp * 128 + c], acc);
    if (c == 0) atomicAdd(&g_z.cnt[gp], ccnt);
}

// ---------------- MLP head ----------------
__global__ void k_mlp(const float* __restrict__ Wm1, const float* __restrict__ bm1,
                      const float* __restrict__ Wm2, const float* __restrict__ bm2,
                      float* __restrict__ out) {
    __shared__ float zs[128], zm[128], hid[128];
    int g = blockIdx.x, c = threadIdx.x;
    float cnt = fmaxf(g_z.cnt[g], 1.0f);
    float xs = g_z.xsum[g * 128 + c];
    zs[c] = xs;
    zm[c] = xs / cnt;
    __syncthreads();
    float acc = bm1[c];
#pragma unroll 8
    for (int k = 0; k < 128; k++)
        acc += zs[k] * Wm1[k * 128 + c] + zm[k] * Wm1[(128 + k) * 128 + c];
    hid[c] = fmaxf(acc, 0.f) * Wm2[c];
    __syncthreads();
    for (int s = 64; s > 0; s >>= 1) {
        if (c < s) hid[c] += hid[c + s];
        __syncthreads();
    }
    if (c == 0) out[g] = hid[0] + bm2[0];
}

// ---------------- host ----------------
extern "C" void kernel_launch(void* const* d_in, const int* in_sizes, int n_in,
                              void* d_out, int out_size) {
    const float *x, *W1, *b1, *W2, *b2, *W3, *b3;
    const float *g1, *be1, *g2, *be2, *g3, *be3;
    const float *Wm1, *bm1, *Wm2, *bm2;
    const int *ei, *batch;

    if (in_sizes[1] == 2 * Ee) {
        x   = (const float*)d_in[0];
        ei  = (const int*)  d_in[1];
        batch = (const int*)d_in[2];
        W1 = (const float*)d_in[3];  b1 = (const float*)d_in[4];
        W2 = (const float*)d_in[5];  b2 = (const float*)d_in[6];
        W3 = (const float*)d_in[7];  b3 = (const float*)d_in[8];
        g1 = (const float*)d_in[9];  be1 = (const float*)d_in[10];
        g2 = (const float*)d_in[11]; be2 = (const float*)d_in[12];
        g3 = (const float*)d_in[13]; be3 = (const float*)d_in[14];
        Wm1 = (const float*)d_in[15]; bm1 = (const float*)d_in[16];
        Wm2 = (const float*)d_in[17]; bm2 = (const float*)d_in[18];
    } else {
        x   = (const float*)d_in[0];
        W1 = (const float*)d_in[1];  b1 = (const float*)d_in[2];
        g1 = (const float*)d_in[3];  be1 = (const float*)d_in[4];
        W2 = (const float*)d_in[5];  b2 = (const float*)d_in[6];
        g2 = (const float*)d_in[7];  be2 = (const float*)d_in[8];
        W3 = (const float*)d_in[9];  b3 = (const float*)d_in[10];
        g3 = (const float*)d_in[11]; be3 = (const float*)d_in[12];
        Wm1 = (const float*)d_in[13]; bm1 = (const float*)d_in[14];
        Wm2 = (const float*)d_in[15]; bm2 = (const float*)d_in[16];
        ei  = (const int*)d_in[17];
        batch = (const int*)d_in[18];
    }

    const int* src = ei;
    const int* dst = ei + Ee;
    float* out = (float*)d_out;

    static cudaStream_t s_side = nullptr;
    static cudaEvent_t s_e1 = nullptr, s_e2 = nullptr;
    if (!s_side) {
        cudaStreamCreateWithFlags(&s_side, cudaStreamNonBlocking);
        cudaEventCreateWithFlags(&s_e1, cudaEventDisableTiming);
        cudaEventCreateWithFlags(&s_e2, cudaEventDisableTiming);
    }

    cudaFuncSetAttribute(gemm_tc, cudaFuncAttributeMaxDynamicSharedMemorySize, SM_TOTAL);

    const int ZB = (Nn + 255) / 256;          // 391
    const int EB = (Ee + 255) / 256;          // 6250
    const int GATB = (Nn + 15) / 16;          // 6250 x 512
    const int POOLB = (Nn + PCHUNK - 1) / PCHUNK;  // 782

    void* zptr = nullptr;
    cudaGetSymbolAddress(&zptr, g_z);
    cudaMemsetAsync(zptr, 0, sizeof(ZBlob), 0);

    k_deg<<<EB, 256>>>(dst);
    cudaEventRecord(s_e1, 0);
    cudaStreamWaitEvent(s_side, s_e1, 0);

    k_prep<<<DINVB + 384, 128>>>(W1, W2, W3);
    k_scan1<<<NBLK, SCAN_BS, 0, s_side>>>();
    gemm_tc<<<TILES, 256, SM_TOTAL>>>(x, 0, 0, 0, nullptr, nullptr);
    k_scan2<<<1, 128, 0, s_side>>>();
    k_scan3<<<ZB, 256, 0, s_side>>>();
    k_fill<<<EB, 256, 0, s_side>>>(src, dst);
    cudaEventRecord(s_e2, s_side);
    cudaStreamWaitEvent(0, s_e2, 0);

    k_gather<<<GATB, 512>>>(b1, 0);

    gemm_tc<<<TILES, 256, SM_TOTAL>>>(nullptr, 1, 1, 0, g1, be1);
    k_gather<<<GATB, 512>>>(b2, 1);

    gemm_tc<<<TILES, 256, SM_TOTAL>>>(nullptr, 2, 2, 1, g2, be2);
    k_gather<<<GATB, 512>>>(b3, 2);

    k_pool<<<POOLB, 128>>>(batch, g3, be3);
    k_mlp<<<Gg, 128>>>(Wm1, bm1, Wm2, bm2, out);
}

// round 15
// speedup vs baseline: 1.0001x; 1.0001x over previous
#include <cuda_runtime.h>
#include <cuda_bf16.h>
#include <cuda_fp16.h>
#include <cstdint>

#define Nn 100000
#define Ee 1600000
#define Hh 128
#define Gg 64
#define EPSf 1e-5f

#define SCAN_BS 1024
#define NBLK ((Nn + SCAN_BS - 1) / SCAN_BS)   // 98
#define BN_REP 4
#define TILES ((Nn + 255) / 256)              // 391
#define DINVB ((Nn + 127) / 128)              // 782

// ------- mma GEMM smem layout (256 rows per tile, A hi-only) -------
#define Pp 136                        // bf16 elements per row (272 B)
#define AIMG_B (256 * Pp * 2)         // 69632 B (A hi)
#define WIMG_B (128 * Pp * 2)         // 34816 B per W image
#define SM_AHI 0
#define SM_W   AIMG_B                 // W hi at +0, W lo at +WIMG_B
#define SM_BN  (AIMG_B + 2 * WIMG_B)  // 139264
#define SM_TOTAL (SM_BN + 1024)       // 140288 B

#define MMA_BF16(d, a, b0, b1) \
    asm volatile("mma.sync.aligned.m16n8k16.row.col.f32.bf16.bf16.f32 " \
        "{%0,%1,%2,%3}, {%4,%5,%6,%7}, {%8,%9}, {%0,%1,%2,%3};" \
        : "+f"((d)[0]), "+f"((d)[1]), "+f"((d)[2]), "+f"((d)[3]) \
        : "r"((a)[0]), "r"((a)[1]), "r"((a)[2]), "r"((a)[3]), "r"(b0), "r"(b1))

// ---------------- device scratch ----------------
struct ZBlob {
    int   deg[Nn];
    int   cursor[Nn];
    float bnsum[3][BN_REP][2 * Hh];
    float xsum[Gg * Hh];
    float cnt[Gg];
};
__device__ ZBlob g_z;
__device__ float g_dinv[Nn];
__device__ int   g_off[Nn + 1];
__device__ int   g_bsum[SCAN_BS];
__device__ int   g_csr[Ee];                       // src only
__device__ __half g_h16[(size_t)Nn * Hh];         // h' = dinv * (A @ W), fp16
__device__ float g_agg[(size_t)Nn * Hh];
__device__ float g_act[(size_t)Nn * Hh];
__device__ __nv_bfloat16 g_wt[3][2][128 * Pp];    // padded W^T bf16 hi/lo images

// ---------------- degree ----------------
__global__ void k_deg(const int* __restrict__ dst) {
    int e = blockIdx.x * blockDim.x + threadIdx.x;
    if (e < Ee) atomicAdd(&g_z.deg[dst[e]], 1);
}

// ---- prep: dinv + W split ----
__global__ void k_prep(const float* __restrict__ W1, const float* __restrict__ W2,
                       const float* __restrict__ W3) {
    int b = blockIdx.x;
    if (b < DINVB) {
        int i = b * 128 + threadIdx.x;
        if (i < Nn) g_dinv[i] = rsqrtf((float)g_z.deg[i] + 1.0f);
    } else {
        int bi = b - DINVB;
        int layer = bi >> 7;
        int n = bi & 127;
        const float* Ws = (layer == 0) ? W1 : (layer == 1) ? W2 : W3;
        int k = threadIdx.x;
        float v = Ws[k * 128 + n];
        __nv_bfloat16 hi = __float2bfloat16(v);
        float lo = v - __bfloat162float(hi);
        g_wt[layer][0][n * Pp + k] = hi;
        g_wt[layer][1][n * Pp + k] = __float2bfloat16(lo);
    }
}

// ---------------- scan ----------------
__global__ void k_scan1() {
    __shared__ int s[SCAN_BS];
    int tid = threadIdx.x;
    int i = blockIdx.x * SCAN_BS + tid;
    int v = (i < Nn) ? g_z.deg[i] : 0;
    s[tid] = v;
    __syncthreads();
    for (int d = 1; d < SCAN_BS; d <<= 1) {
        int t = (tid >= d) ? s[tid - d] : 0;
        __syncthreads();
        s[tid] += t;
        __syncthreads();
    }
    if (i < Nn) g_off[i] = s[tid] - v;
    if (tid == SCAN_BS - 1) g_bsum[blockIdx.x] = s[tid];
}

__global__ void k_scan2() {
    __shared__ int s[128];
    int tid = threadIdx.x;
    int v = (tid < NBLK) ? g_bsum[tid] : 0;
    s[tid] = v;
    __syncthreads();
    for (int d = 1; d < 128; d <<= 1) {
        int t = (tid >= d) ? s[tid - d] : 0;
        __syncthreads();
        s[tid] += t;
        __syncthreads();
    }
    g_bsum[tid] = s[tid] - v;
}

__global__ void k_scan3() {
    int i = blockIdx.x * blockDim.x + threadIdx.x;
    if (i < Nn) g_off[i] += g_bsum[i >> 10];
    if (i == 0) g_off[Nn] = Ee;
}

__global__ void k_fill(const int* __restrict__ src, const int* __restrict__ dst) {
    int e = blockIdx.x * blockDim.x + threadIdx.x;
    if (e >= Ee) return;
    int d = dst[e];
    int pos = g_off[d] + atomicAdd(&g_z.cursor[d], 1);
    g_csr[pos] = src[e];
}

// ---- tensor GEMM: g_h16[M,128] = fp16( dinv * (bf16(A) @ W) ) ----
// 512 threads, 256 rows/tile. Products: Ahi*Whi + Ahi*Wlo.
__global__ __launch_bounds__(512)
void gemm_tc(const float* __restrict__ Ain, int layer, int mode, int bnidx,
             const float* __restrict__ gam, const float* __restrict__ bet) {
    extern __shared__ char sm[];
    float* s_bn = (float*)(sm + SM_BN);
    int tid = threadIdx.x;
    int wid = tid >> 5;
    int lane = tid & 31;
    int gid = lane >> 2;
    int tig = lane & 3;
    int row0 = blockIdx.x * 256;

    // W hi+lo images -> smem
    {
        const uint4* wsrc = (const uint4*)(&g_wt[layer][0][0]);
        uint4* wdst = (uint4*)(sm + SM_W);
        for (int i = tid; i < 4352; i += 512) wdst[i] = wsrc[i];
    }
    // BN scale/shift
    if (mode && tid < 128) {
        float s = 0.f, q = 0.f;
#pragma unroll
        for (int r = 0; r < BN_REP; r++) {
            s += g_z.bnsum[bnidx][r][tid];
            q += g_z.bnsum[bnidx][r][128 + tid];
        }
        float mean = s * (1.0f / (float)Nn);
        float var = q * (1.0f / (float)Nn) - mean * mean;
        float sc = gam[tid] * rsqrtf(var + EPSf);
        s_bn[tid] = sc;
        s_bn[128 + tid] = bet[tid] - mean * sc;
    }
    __syncthreads();

    // A prologue: 512 threads cover 256 rows x 2 halves (hi image only)
    {
        int r = tid & 255;
        int half = tid >> 8;
        int gr = row0 + r;
#pragma unroll
        for (int j = 0; j < 8; j++) {
            int k0 = half * 64 + j * 8;
            float4 va = make_float4(0.f, 0.f, 0.f, 0.f), vb = va;
            if (gr < Nn) {
                if (mode == 0) {
                    const float4* ap = (const float4*)(Ain + (size_t)gr * 128 + k0);
                    va = ap[0]; vb = ap[1];
                } else {
                    const float4* ap = (const float4*)(g_agg + (size_t)gr * 128 + k0);
                    float4 a0 = ap[0], a1 = ap[1];
                    const float4* scp = (const float4*)(s_bn + k0);
                    const float4* shp = (const float4*)(s_bn + 128 + k0);
                    float4 s0 = scp[0], s1 = scp[1], h0 = shp[0], h1 = shp[1];
                    va.x = fmaxf(fmaf(a0.x, s0.x, h0.x), 0.f);
                    va.y = fmaxf(fmaf(a0.y, s0.y, h0.y), 0.f);
                    va.z = fmaxf(fmaf(a0.z, s0.z, h0.z), 0.f);
                    va.w = fmaxf(fmaf(a0.w, s0.w, h0.w), 0.f);
                    vb.x = fmaxf(fmaf(a1.x, s1.x, h1.x), 0.f);
                    vb.y = fmaxf(fmaf(a1.y, s1.y, h1.y), 0.f);
                    vb.z = fmaxf(fmaf(a1.z, s1.z, h1.z), 0.f);
                    vb.w = fmaxf(fmaf(a1.w, s1.w, h1.w), 0.f);
                    if (mode == 2) {
                        const float4* rp = (const float4*)(g_act + (size_t)gr * 128 + k0);
                        float4 r0 = rp[0], r1 = rp[1];
                        va.x += r0.x; va.y += r0.y; va.z += r0.z; va.w += r0.w;
                        vb.x += r1.x; vb.y += r1.y; vb.z += r1.z; vb.w += r1.w;
                    }
                    float4* op = (float4*)(g_act + (size_t)gr * 128 + k0);
                    op[0] = va; op[1] = vb;
                }
            }
            float vv[8] = {va.x, va.y, va.z, va.w, vb.x, vb.y, vb.z, vb.w};
            uint32_t hw[4];
#pragma unroll
            for (int q = 0; q < 4; q++) {
                __nv_bfloat162 hb = __floats2bfloat162_rn(vv[2 * q], vv[2 * q + 1]);
                hw[q] = *(uint32_t*)&hb;
            }
            size_t off = ((size_t)r * Pp + k0) * 2;
            *(uint4*)(sm + SM_AHI + off) = make_uint4(hw[0], hw[1], hw[2], hw[3]);
        }
    }
    __syncthreads();

    // main loop: 16 warps, warp tile 32 rows x 64 cols
    int m0 = (wid >> 1) * 32;
    int nb = (wid & 1) * 64;

    float acc[2][8][4];
#pragma unroll
    for (int t = 0; t < 2; t++)
#pragma unroll
        for (int nt = 0; nt < 8; nt++) {
            acc[t][nt][0] = 0.f; acc[t][nt][1] = 0.f;
            acc[t][nt][2] = 0.f; acc[t][nt][3] = 0.f;
        }

#pragma unroll 1
    for (int kc = 0; kc < 8; kc++) {
        int k0 = kc * 16;
        uint32_t ah[2][4];
#pragma unroll
        for (int t = 0; t < 2; t++) {
            size_t o0 = ((size_t)(m0 + t * 16 + gid) * Pp + k0 + tig * 2) * 2;
            size_t o1 = ((size_t)(m0 + t * 16 + 8 + gid) * Pp + k0 + tig * 2) * 2;
            ah[t][0] = *(const uint32_t*)(sm + SM_AHI + o0);
            ah[t][1] = *(const uint32_t*)(sm + SM_AHI + o1);
            ah[t][2] = *(const uint32_t*)(sm + SM_AHI + o0 + 16);
            ah[t][3] = *(const uint32_t*)(sm + SM_AHI + o1 + 16);
        }
#pragma unroll
        for (int nt = 0; nt < 8; nt++) {
            size_t bo = ((size_t)(nb + nt * 8 + gid) * Pp + k0 + tig * 2) * 2;
            uint32_t bh0 = *(const uint32_t*)(sm + SM_W + bo);
            uint32_t bh1 = *(const uint32_t*)(sm + SM_W + bo + 16);
            uint32_t bl0 = *(const uint32_t*)(sm + SM_W + WIMG_B + bo);
            uint32_t bl1 = *(const uint32_t*)(sm + SM_W + WIMG_B + bo + 16);
#pragma unroll
            for (int t = 0; t < 2; t++) {
                MMA_BF16(acc[t][nt], ah[t], bh0, bh1);
                MMA_BF16(acc[t][nt], ah[t], bl0, bl1);
            }
        }
    }

    // epilogue: scale by dinv, convert to fp16
#pragma unroll
    for (int t = 0; t < 2; t++) {
        int r1 = row0 + m0 + t * 16 + gid;
        int r2 = r1 + 8;
        float dv1 = (r1 < Nn) ? g_dinv[r1] : 0.f;
        float dv2 = (r2 < Nn) ? g_dinv[r2] : 0.f;
#pragma unroll
        for (int nt = 0; nt < 8; nt++) {
            int c2 = (wid & 1) * 32 + nt * 4 + tig;
            if (r1 < Nn) {
                __half2 p = __floats2half2_rn(acc[t][nt][0] * dv1, acc[t][nt][1] * dv1);
                ((uint32_t*)g_h16)[(size_t)r1 * 64 + c2] = *(uint32_t*)&p;
            }
            if (r2 < Nn) {
                __half2 p = __floats2half2_rn(acc[t][nt][2] * dv2, acc[t][nt][3] * dv2);
                ((uint32_t*)g_h16)[(size_t)r2 * 64 + c2] = *(uint32_t*)&p;
            }
        }
    }
}

// ------- gather: warp-staged CSR + shfl broadcast, 8-deep / 4 accumulators -------
__global__ __launch_bounds__(512) void k_gather(const float* __restrict__ bias, int bnidx) {
    __shared__ float ss[16 * 128];

    int tid = threadIdx.x;
    int wloc = tid >> 5;
    int lane = tid & 31;
    int wid = blockIdx.x * 16 + wloc;

    int beg = g_off[wid];
    int end = g_off[wid + 1];
    float dn = g_dinv[wid];

    const uint2* hv = (const uint2*)g_h16;
    uint2 hs = hv[(size_t)wid * 32 + lane];
    float2 f0 = __half22float2(*(__half2*)&hs.x);
    float2 f1 = __half22float2(*(__half2*)&hs.y);
    float4 acc0 = make_float4(f0.x, f0.y, f1.x, f1.y);
    float4 acc1 = make_float4(0.f, 0.f, 0.f, 0.f);
    float4 acc2 = make_float4(0.f, 0.f, 0.f, 0.f);
    float4 acc3 = make_float4(0.f, 0.f, 0.f, 0.f);

    const int* csr = g_csr;
    int e = beg;
    while (e < end) {
        int cnt = end - e;
        if (cnt > 32) cnt = 32;
        int myidx = (lane < cnt) ? csr[e + lane] : 0;
        int j = 0;
        for (; j + 8 <= cnt; j += 8) {
            int s0 = __shfl_sync(0xffffffffu, myidx, j);
            int s1 = __shfl_sync(0xffffffffu, myidx, j + 1);
            int s2 = __shfl_sync(0xffffffffu, myidx, j + 2);
            int s3 = __shfl_sync(0xffffffffu, myidx, j + 3);
            int s4 = __shfl_sync(0xffffffffu, myidx, j + 4);
            int s5 = __shfl_sync(0xffffffffu, myidx, j + 5);
            int s6 = __shfl_sync(0xffffffffu, myidx, j + 6);
            int s7 = __shfl_sync(0xffffffffu, myidx, j + 7);
            uint2 v0 = hv[(size_t)s0 * 32 + lane];
            uint2 v1 = hv[(size_t)s1 * 32 + lane];
            uint2 v2 = hv[(size_t)s2 * 32 + lane];
            uint2 v3 = hv[(size_t)s3 * 32 + lane];
            uint2 v4 = hv[(size_t)s4 * 32 + lane];
            uint2 v5 = hv[(size_t)s5 * 32 + lane];
            uint2 v6 = hv[(size_t)s6 * 32 + lane];
            uint2 v7 = hv[(size_t)s7 * 32 + lane];
            float2 p0 = __half22float2(*(__half2*)&v0.x), q0 = __half22float2(*(__half2*)&v0.y);
            float2 p1 = __half22float2(*(__half2*)&v1.x), q1 = __half22float2(*(__half2*)&v1.y);
            float2 p2 = __half22float2(*(__half2*)&v2.x), q2 = __half22float2(*(__half2*)&v2.y);
            float2 p3 = __half22float2(*(__half2*)&v3.x), q3 = __half22float2(*(__half2*)&v3.y);
            float2 p4 = __half22float2(*(__half2*)&v4.x), q4 = __half22float2(*(__half2*)&v4.y);
            float2 p5 = __half22float2(*(__half2*)&v5.x), q5 = __half22float2(*(__half2*)&v5.y);
            float2 p6 = __half22float2(*(__half2*)&v6.x), q6 = __half22float2(*(__half2*)&v6.y);
            float2 p7 = __half22float2(*(__half2*)&v7.x), q7 = __half22float2(*(__half2*)&v7.y);
            acc0.x += p0.x; acc0.y += p0.y; acc0.z += q0.x; acc0.w += q0.y;
            acc1.x += p1.x; acc1.y += p1.y; acc1.z += q1.x; acc1.w += q1.y;
            acc2.x += p2.x; acc2.y += p2.y; acc2.z += q2.x; acc2.w += q2.y;
            acc3.x += p3.x; acc3.y += p3.y; acc3.z += q3.x; acc3.w += q3.y;
            acc0.x += p4.x; acc0.y += p4.y; acc0.z += q4.x; acc0.w += q4.y;
            acc1.x += p5.x; acc1.y += p5.y; acc1.z += q5.x; acc1.w += q5.y;
            acc2.x += p6.x; acc2.y += p6.y; acc2.z += q6.x; acc2.w += q6.y;
            acc3.x += p7.x; acc3.y += p7.y; acc3.z += q7.x; acc3.w += q7.y;
        }
        for (; j < cnt; j++) {
            int s0 = __shfl_sync(0xffffffffu, myidx, j);
            uint2 v0 = hv[(size_t)s0 * 32 + lane];
            float2 a0 = __half22float2(*(__half2*)&v0.x);
            float2 a1 = __half22float2(*(__half2*)&v0.y);
            acc0.x += a0.x; acc0.y += a0.y; acc0.z += a1.x; acc0.w += a1.y;
        }
        e += cnt;
    }
    acc0.x += acc1.x + acc2.x + acc3.x;
    acc0.y += acc1.y + acc2.y + acc3.y;
    acc0.z += acc1.z + acc2.z + acc3.z;
    acc0.w += acc1.w + acc2.w + acc3.w;

    float4 b4 = ((const float4*)bias)[lane];
    acc0.x = fmaf(acc0.x, dn, b4.x);
    acc0.y = fmaf(acc0.y, dn, b4.y);
    acc0.z = fmaf(acc0.z, dn, b4.z);
    acc0.w = fmaf(acc0.w, dn, b4.w);
    ((float4*)g_agg)[(size_t)wid * 32 + lane] = acc0;

    int base = wloc * 128 + lane * 4;
    ss[base + 0] = acc0.x; ss[base + 1] = acc0.y; ss[base + 2] = acc0.z; ss[base + 3] = acc0.w;
    __syncthreads();

    if (tid < 256) {
        int c = tid & 127;
        int part = tid >> 7;
        float r = 0.f;
        if (part == 0) {
#pragma unroll
            for (int w = 0; w < 16; w++) r += ss[w * 128 + c];
        } else {
#pragma unroll
            for (int w = 0; w < 16; w++) { float v = ss[w * 128 + c]; r = fmaf(v, v, r); }
        }
        atomicAdd(&g_z.bnsum[bnidx][blockIdx.x & (BN_REP - 1)][part * 128 + c], r);
    }
}

// ---------------- pooling with fused layer-3 BN finalize+apply ----------------
#define PCHUNK 128
__global__ void k_pool(const int* __restrict__ batch,
                       const float* __restrict__ gam, const float* __restrict__ bet) {
    int c = threadIdx.x;
    float s = 0.f, q = 0.f;
#pragma unroll
    for (int r = 0; r < BN_REP; r++) {
        s += g_z.bnsum[2][r][c];
        q += g_z.bnsum[2][r][128 + c];
    }
    float mean = s * (1.0f / (float)Nn);
    float var = q * (1.0f / (float)Nn) - mean * mean;
    float sc = gam[c] * rsqrtf(var + EPSf);
    float sh = bet[c] - mean * sc;

    int start = blockIdx.x * PCHUNK;
    if (start >= Nn) return;
    int end = min(start + PCHUNK, Nn);
    float acc = 0.f, ccnt = 0.f;
    int gp = batch[start];
    for (int n = start; n < end; n++) {
        int g = batch[n];
        if (g != gp) {
            atomicAdd(&g_z.xsum[gp * 128 + c], acc);
            if (c == 0) atomicAdd(&g_z.cnt[gp], ccnt);
            acc = 0.f; ccnt = 0.f; gp = g;
        }
        float a = g_agg[(size_t)n * 128 + c];
        float v = fmaxf(fmaf(a, sc, sh), 0.f) + g_act[(size_t)n * 128 + c];
        acc += v;
        ccnt += 1.f;
    }
    atomicAdd(&g_z.xsum[gp * 128 + c], acc);
    if (c == 0) atomicAdd(&g_z.cnt[gp], ccnt);
}

// ---------------- MLP head ----------------
__global__ void k_mlp(const float* __restrict__ Wm1, const float* __restrict__ bm1,
                      const float* __restrict__ Wm2, const float* __restrict__ bm2,
                      float* __restrict__ out) {
    __shared__ float zs[128], zm[128], hid[128];
    int g = blockIdx.x, c = threadIdx.x;
    float cnt = fmaxf(g_z.cnt[g], 1.0f);
    float xs = g_z.xsum[g * 128 + c];
    zs[c] = xs;
    zm[c] = xs / cnt;
    __syncthreads();
    float acc = bm1[c];
#pragma unroll 8
    for (int k = 0; k < 128; k++)
        acc += zs[k] * Wm1[k * 128 + c] + zm[k] * Wm1[(128 + k) * 128 + c];
    hid[c] = fmaxf(acc, 0.f) * Wm2[c];
    __syncthreads();
    for (int s = 64; s > 0; s >>= 1) {
        if (c < s) hid[c] += hid[c + s];
        __syncthreads();
    }
    if (c == 0) out[g] = hid[0] + bm2[0];
}

// ---------------- host ----------------
extern "C" void kernel_launch(void* const* d_in, const int* in_sizes, int n_in,
                              void* d_out, int out_size) {
    const float *x, *W1, *b1, *W2, *b2, *W3, *b3;
    const float *g1, *be1, *g2, *be2, *g3, *be3;
    const float *Wm1, *bm1, *Wm2, *bm2;
    const int *ei, *batch;

    if (in_sizes[1] == 2 * Ee) {
        x   = (const float*)d_in[0];
        ei  = (const int*)  d_in[1];
        batch = (const int*)d_in[2];
        W1 = (const float*)d_in[3];  b1 = (const float*)d_in[4];
        W2 = (const float*)d_in[5];  b2 = (const float*)d_in[6];
        W3 = (const float*)d_in[7];  b3 = (const float*)d_in[8];
        g1 = (const float*)d_in[9];  be1 = (const float*)d_in[10];
        g2 = (const float*)d_in[11]; be2 = (const float*)d_in[12];
        g3 = (const float*)d_in[13]; be3 = (const float*)d_in[14];
        Wm1 = (const float*)d_in[15]; bm1 = (const float*)d_in[16];
        Wm2 = (const float*)d_in[17]; bm2 = (const float*)d_in[18];
    } else {
        x   = (const float*)d_in[0];
        W1 = (const float*)d_in[1];  b1 = (const float*)d_in[2];
        g1 = (const float*)d_in[3];  be1 = (const float*)d_in[4];
        W2 = (const float*)d_in[5];  b2 = (const float*)d_in[6];
        g2 = (const float*)d_in[7];  be2 = (const float*)d_in[8];
        W3 = (const float*)d_in[9];  b3 = (const float*)d_in[10];
        g3 = (const float*)d_in[11]; be3 = (const float*)d_in[12];
        Wm1 = (const float*)d_in[13]; bm1 = (const float*)d_in[14];
        Wm2 = (const float*)d_in[15]; bm2 = (const float*)d_in[16];
        ei  = (const int*)d_in[17];
        batch = (const int*)d_in[18];
    }

    const int* src = ei;
    const int* dst = ei + Ee;
    float* out = (float*)d_out;

    static cudaStream_t s_side = nullptr;
    static cudaEvent_t s_e1 = nullptr, s_e2 = nullptr;
    if (!s_side) {
        cudaStreamCreateWithFlags(&s_side, cudaStreamNonBlocking);
        cudaEventCreateWithFlags(&s_e1, cudaEventDisableTiming);
        cudaEventCreateWithFlags(&s_e2, cudaEventDisableTiming);
    }

    cudaFuncSetAttribute(gemm_tc, cudaFuncAttributeMaxDynamicSharedMemorySize, SM_TOTAL);

    const int ZB = (Nn + 255) / 256;          // 391
    const int EB = (Ee + 255) / 256;          // 6250
    const int GATB = (Nn + 15) / 16;          // 6250 x 512
    const int POOLB = (Nn + PCHUNK - 1) / PCHUNK;  // 782

    void* zptr = nullptr;
    cudaGetSymbolAddress(&zptr, g_z);
    cudaMemsetAsync(zptr, 0, sizeof(ZBlob), 0);

    k_deg<<<EB, 256>>>(dst);
    cudaEventRecord(s_e1, 0);
    cudaStreamWaitEvent(s_side, s_e1, 0);

    k_prep<<<DINVB + 384, 128>>>(W1, W2, W3);
    k_scan1<<<NBLK, SCAN_BS, 0, s_side>>>();
    gemm_tc<<<TILES, 512, SM_TOTAL>>>(x, 0, 0, 0, nullptr, nullptr);
    k_scan2<<<1, 128, 0, s_side>>>();
    k_scan3<<<ZB, 256, 0, s_side>>>();
    k_fill<<<EB, 256, 0, s_side>>>(src, dst);
    cudaEventRecord(s_e2, s_side);
    cudaStreamWaitEvent(0, s_e2, 0);

    k_gather<<<GATB, 512>>>(b1, 0);

    gemm_tc<<<TILES, 512, SM_TOTAL>>>(nullptr, 1, 1, 0, g1, be1);
    k_gather<<<GATB, 512>>>(b2, 1);

    gemm_tc<<<TILES, 512, SM_TOTAL>>>(nullptr, 2, 2, 1, g2, be2);
    k_gather<<<GATB, 512>>>(b3, 2);

    k_pool<<<POOLB, 128>>>(batch, g3, be3);
    k_mlp<<<Gg, 128>>>(Wm1, bm1, Wm2, bm2, out);
}

// round 16
// speedup vs baseline: 1.1420x; 1.1419x over previous
#include <cuda_runtime.h>
#include <cuda_bf16.h>
#include <cuda_fp16.h>
#include <cstdint>

#define Nn 100000
#define Ee 1600000
#define Hh 128
#define Gg 64
#define EPSf 1e-5f

#define SCAN_BS 1024
#define NBLK ((Nn + SCAN_BS - 1) / SCAN_BS)   // 98
#define BN_REP 4
#define TILES ((Nn + 255) / 256)              // 391
#define DINVB ((Nn + 127) / 128)              // 782

// ------- mma GEMM smem layout (256 rows per tile, A hi-only) -------
#define Pp 136                        // bf16 elements per row (272 B)
#define AIMG_B (256 * Pp * 2)         // 69632 B (A hi)
#define WIMG_B (128 * Pp * 2)         // 34816 B per W image
#define SM_AHI 0
#define SM_W   AIMG_B                 // W hi at +0, W lo at +WIMG_B
#define SM_BN  (AIMG_B + 2 * WIMG_B)  // 139264
#define SM_TOTAL (SM_BN + 1024)       // 140288 B

#define MMA_BF16(d, a, b0, b1) \
    asm volatile("mma.sync.aligned.m16n8k16.row.col.f32.bf16.bf16.f32 " \
        "{%0,%1,%2,%3}, {%4,%5,%6,%7}, {%8,%9}, {%0,%1,%2,%3};" \
        : "+f"((d)[0]), "+f"((d)[1]), "+f"((d)[2]), "+f"((d)[3]) \
        : "r"((a)[0]), "r"((a)[1]), "r"((a)[2]), "r"((a)[3]), "r"(b0), "r"(b1))

// ---------------- device scratch ----------------
struct ZBlob {
    int   deg[Nn];
    int   cursor[Nn];
    float bnsum[3][BN_REP][2 * Hh];
    float xsum[Gg * Hh];
    float cnt[Gg];
};
__device__ ZBlob g_z;
__device__ float g_dinv[Nn];
__device__ int   g_off[Nn + 1];
__device__ int   g_bsum[SCAN_BS];
__device__ int   g_csr[Ee];                       // src only
__device__ __half g_h16[(size_t)Nn * Hh];         // h' = dinv * (A @ W), fp16
__device__ float g_agg[(size_t)Nn * Hh];
__device__ float g_act[(size_t)Nn * Hh];
__device__ __nv_bfloat16 g_wt[3][2][128 * Pp];    // padded W^T bf16 hi/lo images

// ---------------- degree ----------------
__global__ void k_deg(const int* __restrict__ dst) {
    int e = blockIdx.x * blockDim.x + threadIdx.x;
    if (e < Ee) atomicAdd(&g_z.deg[dst[e]], 1);
}

// ---- prep: dinv + W split ----
__global__ void k_prep(const float* __restrict__ W1, const float* __restrict__ W2,
                       const float* __restrict__ W3) {
    int b = blockIdx.x;
    if (b < DINVB) {
        int i = b * 128 + threadIdx.x;
        if (i < Nn) g_dinv[i] = rsqrtf((float)g_z.deg[i] + 1.0f);
    } else {
        int bi = b - DINVB;
        int layer = bi >> 7;
        int n = bi & 127;
        const float* Ws = (layer == 0) ? W1 : (layer == 1) ? W2 : W3;
        int k = threadIdx.x;
        float v = Ws[k * 128 + n];
        __nv_bfloat16 hi = __float2bfloat16(v);
        float lo = v - __bfloat162float(hi);
        g_wt[layer][0][n * Pp + k] = hi;
        g_wt[layer][1][n * Pp + k] = __float2bfloat16(lo);
    }
}

// ---------------- scan ----------------
__global__ void k_scan1() {
    __shared__ int s[SCAN_BS];
    int tid = threadIdx.x;
    int i = blockIdx.x * SCAN_BS + tid;
    int v = (i < Nn) ? g_z.deg[i] : 0;
    s[tid] = v;
    __syncthreads();
    for (int d = 1; d < SCAN_BS; d <<= 1) {
        int t = (tid >= d) ? s[tid - d] : 0;
        __syncthreads();
        s[tid] += t;
        __syncthreads();
    }
    if (i < Nn) g_off[i] = s[tid] - v;
    if (tid == SCAN_BS - 1) g_bsum[blockIdx.x] = s[tid];
}

__global__ void k_scan2() {
    __shared__ int s[128];
    int tid = threadIdx.x;
    int v = (tid < NBLK) ? g_bsum[tid] : 0;
    s[tid] = v;
    __syncthreads();
    for (int d = 1; d < 128; d <<= 1) {
        int t = (tid >= d) ? s[tid - d] : 0;
        __syncthreads();
        s[tid] += t;
        __syncthreads();
    }
    g_bsum[tid] = s[tid] - v;
}

__global__ void k_scan3() {
    int i = blockIdx.x * blockDim.x + threadIdx.x;
    if (i < Nn) g_off[i] += g_bsum[i >> 10];
    if (i == 0) g_off[Nn] = Ee;
}

__global__ void k_fill(const int* __restrict__ src, const int* __restrict__ dst) {
    int e = blockIdx.x * blockDim.x + threadIdx.x;
    if (e >= Ee) return;
    int d = dst[e];
    int pos = g_off[d] + atomicAdd(&g_z.cursor[d], 1);
    g_csr[pos] = src[e];
}

// ---- tensor GEMM: g_h16[M,128] = fp16( dinv * (bf16(A) @ W) ) ----
// 512 threads, 256 rows/tile. Products: Ahi*Whi + Ahi*Wlo.
__global__ __launch_bounds__(512)
void gemm_tc(const float* __restrict__ Ain, int layer, int mode, int bnidx,
             const float* __restrict__ gam, const float* __restrict__ bet) {
    extern __shared__ char sm[];
    float* s_bn = (float*)(sm + SM_BN);
    int tid = threadIdx.x;
    int wid = tid >> 5;
    int lane = tid & 31;
    int gid = lane >> 2;
    int tig = lane & 3;
    int row0 = blockIdx.x * 256;

    // W hi+lo images -> smem
    {
        const uint4* wsrc = (const uint4*)(&g_wt[layer][0][0]);
        uint4* wdst = (uint4*)(sm + SM_W);
        for (int i = tid; i < 4352; i += 512) wdst[i] = wsrc[i];
    }
    // BN scale/shift
    if (mode && tid < 128) {
        float s = 0.f, q = 0.f;
#pragma unroll
        for (int r = 0; r < BN_REP; r++) {
            s += g_z.bnsum[bnidx][r][tid];
            q += g_z.bnsum[bnidx][r][128 + tid];
        }
        float mean = s * (1.0f / (float)Nn);
        float var = q * (1.0f / (float)Nn) - mean * mean;
        float sc = gam[tid] * rsqrtf(var + EPSf);
        s_bn[tid] = sc;
        s_bn[128 + tid] = bet[tid] - mean * sc;
    }
    __syncthreads();

    // A prologue: 512 threads cover 256 rows x 2 halves (hi image only)
    {
        int r = tid & 255;
        int half = tid >> 8;
        int gr = row0 + r;
#pragma unroll
        for (int j = 0; j < 8; j++) {
            int k0 = half * 64 + j * 8;
            float4 va = make_float4(0.f, 0.f, 0.f, 0.f), vb = va;
            if (gr < Nn) {
                if (mode == 0) {
                    const float4* ap = (const float4*)(Ain + (size_t)gr * 128 + k0);
                    va = ap[0]; vb = ap[1];
                } else {
                    const float4* ap = (const float4*)(g_agg + (size_t)gr * 128 + k0);
                    float4 a0 = ap[0], a1 = ap[1];
                    const float4* scp = (const float4*)(s_bn + k0);
                    const float4* shp = (const float4*)(s_bn + 128 + k0);
                    float4 s0 = scp[0], s1 = scp[1], h0 = shp[0], h1 = shp[1];
                    va.x = fmaxf(fmaf(a0.x, s0.x, h0.x), 0.f);
                    va.y = fmaxf(fmaf(a0.y, s0.y, h0.y), 0.f);
                    va.z = fmaxf(fmaf(a0.z, s0.z, h0.z), 0.f);
                    va.w = fmaxf(fmaf(a0.w, s0.w, h0.w), 0.f);
                    vb.x = fmaxf(fmaf(a1.x, s1.x, h1.x), 0.f);
                    vb.y = fmaxf(fmaf(a1.y, s1.y, h1.y), 0.f);
                    vb.z = fmaxf(fmaf(a1.z, s1.z, h1.z), 0.f);
                    vb.w = fmaxf(fmaf(a1.w, s1.w, h1.w), 0.f);
                    if (mode == 2) {
                        const float4* rp = (const float4*)(g_act + (size_t)gr * 128 + k0);
                        float4 r0 = rp[0], r1 = rp[1];
                        va.x += r0.x; va.y += r0.y; va.z += r0.z; va.w += r0.w;
                        vb.x += r1.x; vb.y += r1.y; vb.z += r1.z; vb.w += r1.w;
                    }
                    float4* op = (float4*)(g_act + (size_t)gr * 128 + k0);
                    op[0] = va; op[1] = vb;
                }
            }
            float vv[8] = {va.x, va.y, va.z, va.w, vb.x, vb.y, vb.z, vb.w};
            uint32_t hw[4];
#pragma unroll
            for (int q = 0; q < 4; q++) {
                __nv_bfloat162 hb = __floats2bfloat162_rn(vv[2 * q], vv[2 * q + 1]);
                hw[q] = *(uint32_t*)&hb;
            }
            size_t off = ((size_t)r * Pp + k0) * 2;
            *(uint4*)(sm + SM_AHI + off) = make_uint4(hw[0], hw[1], hw[2], hw[3]);
        }
    }
    __syncthreads();

    // main loop: 16 warps, warp tile 32 rows x 64 cols
    int m0 = (wid >> 1) * 32;
    int nb = (wid & 1) * 64;

    float acc[2][8][4];
#pragma unroll
    for (int t = 0; t < 2; t++)
#pragma unroll
        for (int nt = 0; nt < 8; nt++) {
            acc[t][nt][0] = 0.f; acc[t][nt][1] = 0.f;
            acc[t][nt][2] = 0.f; acc[t][nt][3] = 0.f;
        }

#pragma unroll 1
    for (int kc = 0; kc < 8; kc++) {
        int k0 = kc * 16;
        uint32_t ah[2][4];
#pragma unroll
        for (int t = 0; t < 2; t++) {
            size_t o0 = ((size_t)(m0 + t * 16 + gid) * Pp + k0 + tig * 2) * 2;
            size_t o1 = ((size_t)(m0 + t * 16 + 8 + gid) * Pp + k0 + tig * 2) * 2;
            ah[t][0] = *(const uint32_t*)(sm + SM_AHI + o0);
            ah[t][1] = *(const uint32_t*)(sm + SM_AHI + o1);
            ah[t][2] = *(const uint32_t*)(sm + SM_AHI + o0 + 16);
            ah[t][3] = *(const uint32_t*)(sm + SM_AHI + o1 + 16);
        }
#pragma unroll
        for (int nt = 0; nt < 8; nt++) {
            size_t bo = ((size_t)(nb + nt * 8 + gid) * Pp + k0 + tig * 2) * 2;
            uint32_t bh0 = *(const uint32_t*)(sm + SM_W + bo);
            uint32_t bh1 = *(const uint32_t*)(sm + SM_W + bo + 16);
            uint32_t bl0 = *(const uint32_t*)(sm + SM_W + WIMG_B + bo);
            uint32_t bl1 = *(const uint32_t*)(sm + SM_W + WIMG_B + bo + 16);
#pragma unroll
            for (int t = 0; t < 2; t++) {
                MMA_BF16(acc[t][nt], ah[t], bh0, bh1);
                MMA_BF16(acc[t][nt], ah[t], bl0, bl1);
            }
        }
    }

    // epilogue: scale by dinv, convert to fp16
#pragma unroll
    for (int t = 0; t < 2; t++) {
        int r1 = row0 + m0 + t * 16 + gid;
        int r2 = r1 + 8;
        float dv1 = (r1 < Nn) ? g_dinv[r1] : 0.f;
        float dv2 = (r2 < Nn) ? g_dinv[r2] : 0.f;
#pragma unroll
        for (int nt = 0; nt < 8; nt++) {
            int c2 = (wid & 1) * 32 + nt * 4 + tig;
            if (r1 < Nn) {
                __half2 p = __floats2half2_rn(acc[t][nt][0] * dv1, acc[t][nt][1] * dv1);
                ((uint32_t*)g_h16)[(size_t)r1 * 64 + c2] = *(uint32_t*)&p;
            }
            if (r2 < Nn) {
                __half2 p = __floats2half2_rn(acc[t][nt][2] * dv2, acc[t][nt][3] * dv2);
                ((uint32_t*)g_h16)[(size_t)r2 * 64 + c2] = *(uint32_t*)&p;
            }
        }
    }
}

// ------- gather (R13): warp-staged CSR + shfl broadcast, 4-deep / 2 accumulators -------
// agg[d] = dinv[d] * (h'[d] + sum_e h'[src_e]) + bias
__global__ __launch_bounds__(512) void k_gather(const float* __restrict__ bias, int bnidx) {
    __shared__ float ss[16 * 128];

    int tid = threadIdx.x;
    int wloc = tid >> 5;
    int lane = tid & 31;
    int wid = blockIdx.x * 16 + wloc;

    int beg = g_off[wid];
    int end = g_off[wid + 1];
    float dn = g_dinv[wid];

    const uint2* hv = (const uint2*)g_h16;
    uint2 hs = hv[(size_t)wid * 32 + lane];
    float2 f0 = __half22float2(*(__half2*)&hs.x);
    float2 f1 = __half22float2(*(__half2*)&hs.y);
    float4 acc = make_float4(f0.x, f0.y, f1.x, f1.y);
    float4 acc2 = make_float4(0.f, 0.f, 0.f, 0.f);

    const int* csr = g_csr;
    int e = beg;
    while (e < end) {
        int cnt = end - e;
        if (cnt > 32) cnt = 32;
        int myidx = (lane < cnt) ? csr[e + lane] : 0;
        int j = 0;
        for (; j + 4 <= cnt; j += 4) {
            int s0 = __shfl_sync(0xffffffffu, myidx, j);
            int s1 = __shfl_sync(0xffffffffu, myidx, j + 1);
            int s2 = __shfl_sync(0xffffffffu, myidx, j + 2);
            int s3 = __shfl_sync(0xffffffffu, myidx, j + 3);
            uint2 v0 = hv[(size_t)s0 * 32 + lane];
            uint2 v1 = hv[(size_t)s1 * 32 + lane];
            uint2 v2 = hv[(size_t)s2 * 32 + lane];
            uint2 v3 = hv[(size_t)s3 * 32 + lane];
            float2 a0 = __half22float2(*(__half2*)&v0.x), a1 = __half22float2(*(__half2*)&v0.y);
            float2 b0 = __half22float2(*(__half2*)&v1.x), b1 = __half22float2(*(__half2*)&v1.y);
            float2 d0 = __half22float2(*(__half2*)&v2.x), d1 = __half22float2(*(__half2*)&v2.y);
            float2 e0 = __half22float2(*(__half2*)&v3.x), e1 = __half22float2(*(__half2*)&v3.y);
            acc.x += a0.x + d0.x;  acc.y += a0.y + d0.y;
            acc.z += a1.x + d1.x;  acc.w += a1.y + d1.y;
            acc2.x += b0.x + e0.x; acc2.y += b0.y + e0.y;
            acc2.z += b1.x + e1.x; acc2.w += b1.y + e1.y;
        }
        for (; j < cnt; j++) {
            int s0 = __shfl_sync(0xffffffffu, myidx, j);
            uint2 v0 = hv[(size_t)s0 * 32 + lane];
            float2 a0 = __half22float2(*(__half2*)&v0.x);
            float2 a1 = __half22float2(*(__half2*)&v0.y);
            acc.x += a0.x; acc.y += a0.y; acc.z += a1.x; acc.w += a1.y;
        }
        e += cnt;
    }
    acc.x += acc2.x; acc.y += acc2.y; acc.z += acc2.z; acc.w += acc2.w;

    float4 b4 = ((const float4*)bias)[lane];
    acc.x = fmaf(acc.x, dn, b4.x);
    acc.y = fmaf(acc.y, dn, b4.y);
    acc.z = fmaf(acc.z, dn, b4.z);
    acc.w = fmaf(acc.w, dn, b4.w);
    ((float4*)g_agg)[(size_t)wid * 32 + lane] = acc;

    int base = wloc * 128 + lane * 4;
    ss[base + 0] = acc.x; ss[base + 1] = acc.y; ss[base + 2] = acc.z; ss[base + 3] = acc.w;
    __syncthreads();

    if (tid < 256) {
        int c = tid & 127;
        int part = tid >> 7;
        float r = 0.f;
        if (part == 0) {
#pragma unroll
            for (int w = 0; w < 16; w++) r += ss[w * 128 + c];
        } else {
#pragma unroll
            for (int w = 0; w < 16; w++) { float v = ss[w * 128 + c]; r = fmaf(v, v, r); }
        }
        atomicAdd(&g_z.bnsum[bnidx][blockIdx.x & (BN_REP - 1)][part * 128 + c], r);
    }
}

// ---------------- pooling with fused layer-3 BN finalize+apply ----------------
#define PCHUNK 128
__global__ void k_pool(const int* __restrict__ batch,
                       const float* __restrict__ gam, const float* __restrict__ bet) {
    int c = threadIdx.x;
    float s = 0.f, q = 0.f;
#pragma unroll
    for (int r = 0; r < BN_REP; r++) {
        s += g_z.bnsum[2][r][c];
        q += g_z.bnsum[2][r][128 + c];
    }
    float mean = s * (1.0f / (float)Nn);
    float var = q * (1.0f / (float)Nn) - mean * mean;
    float sc = gam[c] * rsqrtf(var + EPSf);
    float sh = bet[c] - mean * sc;

    int start = blockIdx.x * PCHUNK;
    if (start >= Nn) return;
    int end = min(start + PCHUNK, Nn);
    float acc = 0.f, ccnt = 0.f;
    int gp = batch[start];
    for (int n = start; n < end; n++) {
        int g = batch[n];
        if (g != gp) {
            atomicAdd(&g_z.xsum[gp * 128 + c], acc);
            if (c == 0) atomicAdd(&g_z.cnt[gp], ccnt);
            acc = 0.f; ccnt = 0.f; gp = g;
        }
        float a = g_agg[(size_t)n * 128 + c];
        float v = fmaxf(fmaf(a, sc, sh), 0.f) + g_act[(size_t)n * 128 + c];
        acc += v;
        ccnt += 1.f;
    }
    atomicAdd(&g_z.xsum[gp * 128 + c], acc);
    if (c == 0) atomicAdd(&g_z.cnt[gp], ccnt);
}

// ---------------- MLP head ----------------
__global__ void k_mlp(const float* __restrict__ Wm1, const float* __restrict__ bm1,
                      const float* __restrict__ Wm2, const float* __restrict__ bm2,
                      float* __restrict__ out) {
    __shared__ float zs[128], zm[128], hid[128];
    int g = blockIdx.x, c = threadIdx.x;
    float cnt = fmaxf(g_z.cnt[g], 1.0f);
    float xs = g_z.xsum[g * 128 + c];
    zs[c] = xs;
    zm[c] = xs / cnt;
    __syncthreads();
    float acc = bm1[c];
#pragma unroll 8
    for (int k = 0; k < 128; k++)
        acc += zs[k] * Wm1[k * 128 + c] + zm[k] * Wm1[(128 + k) * 128 + c];
    hid[c] = fmaxf(acc, 0.f) * Wm2[c];
    __syncthreads();
    for (int s = 64; s > 0; s >>= 1) {
        if (c < s) hid[c] += hid[c + s];
        __syncthreads();
    }
    if (c == 0) out[g] = hid[0] + bm2[0];
}

// ---------------- host ----------------
extern "C" void kernel_launch(void* const* d_in, const int* in_sizes, int n_in,
                              void* d_out, int out_size) {
    const float *x, *W1, *b1, *W2, *b2, *W3, *b3;
    const float *g1, *be1, *g2, *be2, *g3, *be3;
    const float *Wm1, *bm1, *Wm2, *bm2;
    const int *ei, *batch;

    if (in_sizes[1] == 2 * Ee) {
        x   = (const float*)d_in[0];
        ei  = (const int*)  d_in[1];
        batch = (const int*)d_in[2];
        W1 = (const float*)d_in[3];  b1 = (const float*)d_in[4];
        W2 = (const float*)d_in[5];  b2 = (const float*)d_in[6];
        W3 = (const float*)d_in[7];  b3 = (const float*)d_in[8];
        g1 = (const float*)d_in[9];  be1 = (const float*)d_in[10];
        g2 = (const float*)d_in[11]; be2 = (const float*)d_in[12];
        g3 = (const float*)d_in[13]; be3 = (const float*)d_in[14];
        Wm1 = (const float*)d_in[15]; bm1 = (const float*)d_in[16];
        Wm2 = (const float*)d_in[17]; bm2 = (const float*)d_in[18];
    } else {
        x   = (const float*)d_in[0];
        W1 = (const float*)d_in[1];  b1 = (const float*)d_in[2];
        g1 = (const float*)d_in[3];  be1 = (const float*)d_in[4];
        W2 = (const float*)d_in[5];  b2 = (const float*)d_in[6];
        g2 = (const float*)d_in[7];  be2 = (const float*)d_in[8];
        W3 = (const float*)d_in[9];  b3 = (const float*)d_in[10];
        g3 = (const float*)d_in[11]; be3 = (const float*)d_in[12];
        Wm1 = (const float*)d_in[13]; bm1 = (const float*)d_in[14];
        Wm2 = (const float*)d_in[15]; bm2 = (const float*)d_in[16];
        ei  = (const int*)d_in[17];
        batch = (const int*)d_in[18];
    }

    const int* src = ei;
    const int* dst = ei + Ee;
    float* out = (float*)d_out;

    static cudaStream_t s_side = nullptr;
    static cudaEvent_t s_e1 = nullptr, s_e2 = nullptr;
    if (!s_side) {
        cudaStreamCreateWithFlags(&s_side, cudaStreamNonBlocking);
        cudaEventCreateWithFlags(&s_e1, cudaEventDisableTiming);
        cudaEventCreateWithFlags(&s_e2, cudaEventDisableTiming);
    }

    cudaFuncSetAttribute(gemm_tc, cudaFuncAttributeMaxDynamicSharedMemorySize, SM_TOTAL);

    const int ZB = (Nn + 255) / 256;          // 391
    const int EB = (Ee + 255) / 256;          // 6250
    const int GATB = (Nn + 15) / 16;          // 6250 x 512
    const int POOLB = (Nn + PCHUNK - 1) / PCHUNK;  // 782

    void* zptr = nullptr;
    cudaGetSymbolAddress(&zptr, g_z);
    cudaMemsetAsync(zptr, 0, sizeof(ZBlob), 0);

    k_deg<<<EB, 256>>>(dst);
    cudaEventRecord(s_e1, 0);
    cudaStreamWaitEvent(s_side, s_e1, 0);

    k_prep<<<DINVB + 384, 128>>>(W1, W2, W3);
    k_scan1<<<NBLK, SCAN_BS, 0, s_side>>>();
    gemm_tc<<<TILES, 512, SM_TOTAL>>>(x, 0, 0, 0, nullptr, nullptr);
    k_scan2<<<1, 128, 0, s_side>>>();
    k_scan3<<<ZB, 256, 0, s_side>>>();
    k_fill<<<EB, 256, 0, s_side>>>(src, dst);
    cudaEventRecord(s_e2, s_side);
    cudaStreamWaitEvent(0, s_e2, 0);

    k_gather<<<GATB, 512>>>(b1, 0);

    gemm_tc<<<TILES, 512, SM_TOTAL>>>(nullptr, 1, 1, 0, g1, be1);
    k_gather<<<GATB, 512>>>(b2, 1);

    gemm_tc<<<TILES, 512, SM_TOTAL>>>(nullptr, 2, 2, 1, g2, be2);
    k_gather<<<GATB, 512>>>(b3, 2);

    k_pool<<<POOLB, 128>>>(batch, g3, be3);
    k_mlp<<<Gg, 128>>>(Wm1, bm1, Wm2, bm2, out);
}

// round 17
// speedup vs baseline: 1.2773x; 1.1184x over previous
#include <cuda_runtime.h>
#include <cuda_bf16.h>
#include <cuda_fp16.h>
#include <cstdint>

#define Nn 100000
#define Ee 1600000
#define Hh 128
#define Gg 64
#define EPSf 1e-5f

#define SCAN_BS 1024
#define NBLK ((Nn + SCAN_BS - 1) / SCAN_BS)   // 98
#define BN_REP 4
#define TILES ((Nn + 255) / 256)              // 391
#define DINVB ((Nn + 127) / 128)              // 782

// ------- mma GEMM smem layout (256 rows per tile, A hi-only) -------
#define Pp 136                        // bf16 elements per row (272 B)
#define AIMG_B (256 * Pp * 2)         // 69632 B (A hi)
#define WIMG_B (128 * Pp * 2)         // 34816 B per W image
#define SM_AHI 0
#define SM_W   AIMG_B                 // W hi at +0, W lo at +WIMG_B
#define SM_BN  (AIMG_B + 2 * WIMG_B)  // 139264
#define SM_TOTAL (SM_BN + 1024)       // 140288 B

#define MMA_BF16(d, a, b0, b1) \
    asm volatile("mma.sync.aligned.m16n8k16.row.col.f32.bf16.bf16.f32 " \
        "{%0,%1,%2,%3}, {%4,%5,%6,%7}, {%8,%9}, {%0,%1,%2,%3};" \
        : "+f"((d)[0]), "+f"((d)[1]), "+f"((d)[2]), "+f"((d)[3]) \
        : "r"((a)[0]), "r"((a)[1]), "r"((a)[2]), "r"((a)[3]), "r"(b0), "r"(b1))

// ---------------- device scratch ----------------
struct ZBlob {
    int   deg[Nn];
    int   cursor[Nn];
    float bnsum[3][BN_REP][2 * Hh];
    float xsum[Gg * Hh];
    float cnt[Gg];
};
__device__ ZBlob g_z;
__device__ float g_dinv[Nn];
__device__ int   g_off[Nn + 1];
__device__ int   g_bsum[SCAN_BS];
__device__ int   g_csr[Ee];                       // src only
__device__ __half g_h16[(size_t)Nn * Hh];         // h' = dinv * (A @ W), fp16
__device__ __half g_agg16[(size_t)Nn * Hh];       // aggregated pre-BN, fp16
__device__ __half g_act16[(size_t)Nn * Hh];       // activations / residual, fp16
__device__ __nv_bfloat16 g_wt[3][2][128 * Pp];    // padded W^T bf16 hi/lo images

// ---------------- degree ----------------
__global__ void k_deg(const int* __restrict__ dst) {
    int e = blockIdx.x * blockDim.x + threadIdx.x;
    if (e < Ee) atomicAdd(&g_z.deg[dst[e]], 1);
}

// ---- prep: dinv + W split ----
__global__ void k_prep(const float* __restrict__ W1, const float* __restrict__ W2,
                       const float* __restrict__ W3) {
    int b = blockIdx.x;
    if (b < DINVB) {
        int i = b * 128 + threadIdx.x;
        if (i < Nn) g_dinv[i] = rsqrtf((float)g_z.deg[i] + 1.0f);
    } else {
        int bi = b - DINVB;
        int layer = bi >> 7;
        int n = bi & 127;
        const float* Ws = (layer == 0) ? W1 : (layer == 1) ? W2 : W3;
        int k = threadIdx.x;
        float v = Ws[k * 128 + n];
        __nv_bfloat16 hi = __float2bfloat16(v);
        float lo = v - __bfloat162float(hi);
        g_wt[layer][0][n * Pp + k] = hi;
        g_wt[layer][1][n * Pp + k] = __float2bfloat16(lo);
    }
}

// ---------------- scan ----------------
__global__ void k_scan1() {
    __shared__ int s[SCAN_BS];
    int tid = threadIdx.x;
    int i = blockIdx.x * SCAN_BS + tid;
    int v = (i < Nn) ? g_z.deg[i] : 0;
    s[tid] = v;
    __syncthreads();
    for (int d = 1; d < SCAN_BS; d <<= 1) {
        int t = (tid >= d) ? s[tid - d] : 0;
        __syncthreads();
        s[tid] += t;
        __syncthreads();
    }
    if (i < Nn) g_off[i] = s[tid] - v;
    if (tid == SCAN_BS - 1) g_bsum[blockIdx.x] = s[tid];
}

__global__ void k_scan2() {
    __shared__ int s[128];
    int tid = threadIdx.x;
    int v = (tid < NBLK) ? g_bsum[tid] : 0;
    s[tid] = v;
    __syncthreads();
    for (int d = 1; d < 128; d <<= 1) {
        int t = (tid >= d) ? s[tid - d] : 0;
        __syncthreads();
        s[tid] += t;
        __syncthreads();
    }
    g_bsum[tid] = s[tid] - v;
}

__global__ void k_scan3() {
    int i = blockIdx.x * blockDim.x + threadIdx.x;
    if (i < Nn) g_off[i] += g_bsum[i >> 10];
    if (i == 0) g_off[Nn] = Ee;
}

__global__ void k_fill(const int* __restrict__ src, const int* __restrict__ dst) {
    int e = blockIdx.x * blockDim.x + threadIdx.x;
    if (e >= Ee) return;
    int d = dst[e];
    int pos = g_off[d] + atomicAdd(&g_z.cursor[d], 1);
    g_csr[pos] = src[e];
}

// ---- tensor GEMM: g_h16[M,128] = fp16( dinv * (bf16(A) @ W) ) ----
// 512 threads, 256 rows/tile. Products: Ahi*Whi + Ahi*Wlo.
// mode 0: A = Ain (fp32); mode 1: A = relu(bn(agg16)) -> also act16;
// mode 2: A = relu(bn(agg16)) + act16 -> also act16
__global__ __launch_bounds__(512)
void gemm_tc(const float* __restrict__ Ain, int layer, int mode, int bnidx,
             const float* __restrict__ gam, const float* __restrict__ bet) {
    extern __shared__ char sm[];
    float* s_bn = (float*)(sm + SM_BN);
    int tid = threadIdx.x;
    int wid = tid >> 5;
    int lane = tid & 31;
    int gid = lane >> 2;
    int tig = lane & 3;
    int row0 = blockIdx.x * 256;

    // W hi+lo images -> smem
    {
        const uint4* wsrc = (const uint4*)(&g_wt[layer][0][0]);
        uint4* wdst = (uint4*)(sm + SM_W);
        for (int i = tid; i < 4352; i += 512) wdst[i] = wsrc[i];
    }
    // BN scale/shift
    if (mode && tid < 128) {
        float s = 0.f, q = 0.f;
#pragma unroll
        for (int r = 0; r < BN_REP; r++) {
            s += g_z.bnsum[bnidx][r][tid];
            q += g_z.bnsum[bnidx][r][128 + tid];
        }
        float mean = s * (1.0f / (float)Nn);
        float var = q * (1.0f / (float)Nn) - mean * mean;
        float sc = gam[tid] * rsqrtf(var + EPSf);
        s_bn[tid] = sc;
        s_bn[128 + tid] = bet[tid] - mean * sc;
    }
    __syncthreads();

    // A prologue: 512 threads cover 256 rows x 2 halves (hi image only)
    {
        int r = tid & 255;
        int half = tid >> 8;
        int gr = row0 + r;
#pragma unroll
        for (int j = 0; j < 8; j++) {
            int k0 = half * 64 + j * 8;
            float vv[8] = {0.f, 0.f, 0.f, 0.f, 0.f, 0.f, 0.f, 0.f};
            if (gr < Nn) {
                if (mode == 0) {
                    const float4* ap = (const float4*)(Ain + (size_t)gr * 128 + k0);
                    float4 a0 = ap[0], a1 = ap[1];
                    vv[0] = a0.x; vv[1] = a0.y; vv[2] = a0.z; vv[3] = a0.w;
                    vv[4] = a1.x; vv[5] = a1.y; vv[6] = a1.z; vv[7] = a1.w;
                } else {
                    uint4 av = *(const uint4*)(g_agg16 + (size_t)gr * 128 + k0);
                    __half2* ah2 = (__half2*)&av;
                    float aa[8];
#pragma unroll
                    for (int q = 0; q < 4; q++) {
                        float2 f = __half22float2(ah2[q]);
                        aa[2 * q] = f.x; aa[2 * q + 1] = f.y;
                    }
                    float rr[8] = {0.f, 0.f, 0.f, 0.f, 0.f, 0.f, 0.f, 0.f};
                    if (mode == 2) {
                        uint4 rv = *(const uint4*)(g_act16 + (size_t)gr * 128 + k0);
                        __half2* rh2 = (__half2*)&rv;
#pragma unroll
                        for (int q = 0; q < 4; q++) {
                            float2 f = __half22float2(rh2[q]);
                            rr[2 * q] = f.x; rr[2 * q + 1] = f.y;
                        }
                    }
#pragma unroll
                    for (int q = 0; q < 8; q++) {
                        float sc = s_bn[k0 + q];
                        float sh = s_bn[128 + k0 + q];
                        vv[q] = fmaxf(fmaf(aa[q], sc, sh), 0.f) + rr[q];
                    }
                    uint4 ov;
                    __half2* oh2 = (__half2*)&ov;
#pragma unroll
                    for (int q = 0; q < 4; q++)
                        oh2[q] = __floats2half2_rn(vv[2 * q], vv[2 * q + 1]);
                    *(uint4*)(g_act16 + (size_t)gr * 128 + k0) = ov;
                }
            }
            uint32_t hw[4];
#pragma unroll
            for (int q = 0; q < 4; q++) {
                __nv_bfloat162 hb = __floats2bfloat162_rn(vv[2 * q], vv[2 * q + 1]);
                hw[q] = *(uint32_t*)&hb;
            }
            size_t off = ((size_t)r * Pp + k0) * 2;
            *(uint4*)(sm + SM_AHI + off) = make_uint4(hw[0], hw[1], hw[2], hw[3]);
        }
    }
    __syncthreads();

    // main loop: 16 warps, warp tile 32 rows x 64 cols
    int m0 = (wid >> 1) * 32;
    int nb = (wid & 1) * 64;

    float acc[2][8][4];
#pragma unroll
    for (int t = 0; t < 2; t++)
#pragma unroll
        for (int nt = 0; nt < 8; nt++) {
            acc[t][nt][0] = 0.f; acc[t][nt][1] = 0.f;
            acc[t][nt][2] = 0.f; acc[t][nt][3] = 0.f;
        }

#pragma unroll 1
    for (int kc = 0; kc < 8; kc++) {
        int k0 = kc * 16;
        uint32_t ah[2][4];
#pragma unroll
        for (int t = 0; t < 2; t++) {
            size_t o0 = ((size_t)(m0 + t * 16 + gid) * Pp + k0 + tig * 2) * 2;
            size_t o1 = ((size_t)(m0 + t * 16 + 8 + gid) * Pp + k0 + tig * 2) * 2;
            ah[t][0] = *(const uint32_t*)(sm + SM_AHI + o0);
            ah[t][1] = *(const uint32_t*)(sm + SM_AHI + o1);
            ah[t][2] = *(const uint32_t*)(sm + SM_AHI + o0 + 16);
            ah[t][3] = *(const uint32_t*)(sm + SM_AHI + o1 + 16);
        }
#pragma unroll
        for (int nt = 0; nt < 8; nt++) {
            size_t bo = ((size_t)(nb + nt * 8 + gid) * Pp + k0 + tig * 2) * 2;
            uint32_t bh0 = *(const uint32_t*)(sm + SM_W + bo);
            uint32_t bh1 = *(const uint32_t*)(sm + SM_W + bo + 16);
            uint32_t bl0 = *(const uint32_t*)(sm + SM_W + WIMG_B + bo);
            uint32_t bl1 = *(const uint32_t*)(sm + SM_W + WIMG_B + bo + 16);
#pragma unroll
            for (int t = 0; t < 2; t++) {
                MMA_BF16(acc[t][nt], ah[t], bh0, bh1);
                MMA_BF16(acc[t][nt], ah[t], bl0, bl1);
            }
        }
    }

    // epilogue: scale by dinv, convert to fp16
#pragma unroll
    for (int t = 0; t < 2; t++) {
        int r1 = row0 + m0 + t * 16 + gid;
        int r2 = r1 + 8;
        float dv1 = (r1 < Nn) ? g_dinv[r1] : 0.f;
        float dv2 = (r2 < Nn) ? g_dinv[r2] : 0.f;
#pragma unroll
        for (int nt = 0; nt < 8; nt++) {
            int c2 = (wid & 1) * 32 + nt * 4 + tig;
            if (r1 < Nn) {
                __half2 p = __floats2half2_rn(acc[t][nt][0] * dv1, acc[t][nt][1] * dv1);
                ((uint32_t*)g_h16)[(size_t)r1 * 64 + c2] = *(uint32_t*)&p;
            }
            if (r2 < Nn) {
                __half2 p = __floats2half2_rn(acc[t][nt][2] * dv2, acc[t][nt][3] * dv2);
                ((uint32_t*)g_h16)[(size_t)r2 * 64 + c2] = *(uint32_t*)&p;
            }
        }
    }
}

// ------- gather: warp-staged CSR + shfl broadcast, 4-deep / 2 accumulators -------
// agg16[d] = fp16( dinv[d] * (h'[d] + sum_e h'[src_e]) + bias )
__global__ __launch_bounds__(512) void k_gather(const float* __restrict__ bias, int bnidx) {
    __shared__ float ss[16 * 128];

    int tid = threadIdx.x;
    int wloc = tid >> 5;
    int lane = tid & 31;
    int wid = blockIdx.x * 16 + wloc;

    int beg = g_off[wid];
    int end = g_off[wid + 1];
    float dn = g_dinv[wid];

    const uint2* hv = (const uint2*)g_h16;
    uint2 hs = hv[(size_t)wid * 32 + lane];
    float2 f0 = __half22float2(*(__half2*)&hs.x);
    float2 f1 = __half22float2(*(__half2*)&hs.y);
    float4 acc = make_float4(f0.x, f0.y, f1.x, f1.y);
    float4 acc2 = make_float4(0.f, 0.f, 0.f, 0.f);

    const int* csr = g_csr;
    int e = beg;
    while (e < end) {
        int cnt = end - e;
        if (cnt > 32) cnt = 32;
        int myidx = (lane < cnt) ? csr[e + lane] : 0;
        int j = 0;
        for (; j + 4 <= cnt; j += 4) {
            int s0 = __shfl_sync(0xffffffffu, myidx, j);
            int s1 = __shfl_sync(0xffffffffu, myidx, j + 1);
            int s2 = __shfl_sync(0xffffffffu, myidx, j + 2);
            int s3 = __shfl_sync(0xffffffffu, myidx, j + 3);
            uint2 v0 = hv[(size_t)s0 * 32 + lane];
            uint2 v1 = hv[(size_t)s1 * 32 + lane];
            uint2 v2 = hv[(size_t)s2 * 32 + lane];
            uint2 v3 = hv[(size_t)s3 * 32 + lane];
            float2 a0 = __half22float2(*(__half2*)&v0.x), a1 = __half22float2(*(__half2*)&v0.y);
            float2 b0 = __half22float2(*(__half2*)&v1.x), b1 = __half22float2(*(__half2*)&v1.y);
            float2 d0 = __half22float2(*(__half2*)&v2.x), d1 = __half22float2(*(__half2*)&v2.y);
            float2 e0 = __half22float2(*(__half2*)&v3.x), e1 = __half22float2(*(__half2*)&v3.y);
            acc.x += a0.x + d0.x;  acc.y += a0.y + d0.y;
            acc.z += a1.x + d1.x;  acc.w += a1.y + d1.y;
            acc2.x += b0.x + e0.x; acc2.y += b0.y + e0.y;
            acc2.z += b1.x + e1.x; acc2.w += b1.y + e1.y;
        }
        for (; j < cnt; j++) {
            int s0 = __shfl_sync(0xffffffffu, myidx, j);
            uint2 v0 = hv[(size_t)s0 * 32 + lane];
            float2 a0 = __half22float2(*(__half2*)&v0.x);
            float2 a1 = __half22float2(*(__half2*)&v0.y);
            acc.x += a0.x; acc.y += a0.y; acc.z += a1.x; acc.w += a1.y;
        }
        e += cnt;
    }
    acc.x += acc2.x; acc.y += acc2.y; acc.z += acc2.z; acc.w += acc2.w;

    float4 b4 = ((const float4*)bias)[lane];
    acc.x = fmaf(acc.x, dn, b4.x);
    acc.y = fmaf(acc.y, dn, b4.y);
    acc.z = fmaf(acc.z, dn, b4.z);
    acc.w = fmaf(acc.w, dn, b4.w);

    // store agg as fp16
    {
        __half2 p0 = __floats2half2_rn(acc.x, acc.y);
        __half2 p1 = __floats2half2_rn(acc.z, acc.w);
        uint2 st;
        st.x = *(uint32_t*)&p0;
        st.y = *(uint32_t*)&p1;
        ((uint2*)g_agg16)[(size_t)wid * 32 + lane] = st;
    }

    int base = wloc * 128 + lane * 4;
    ss[base + 0] = acc.x; ss[base + 1] = acc.y; ss[base + 2] = acc.z; ss[base + 3] = acc.w;
    __syncthreads();

    if (tid < 256) {
        int c = tid & 127;
        int part = tid >> 7;
        float r = 0.f;
        if (part == 0) {
#pragma unroll
            for (int w = 0; w < 16; w++) r += ss[w * 128 + c];
        } else {
#pragma unroll
            for (int w = 0; w < 16; w++) { float v = ss[w * 128 + c]; r = fmaf(v, v, r); }
        }
        atomicAdd(&g_z.bnsum[bnidx][blockIdx.x & (BN_REP - 1)][part * 128 + c], r);
    }
}

// ---------------- pooling with fused layer-3 BN finalize+apply ----------------
#define PCHUNK 128
__global__ void k_pool(const int* __restrict__ batch,
                       const float* __restrict__ gam, const float* __restrict__ bet) {
    int c = threadIdx.x;
    float s = 0.f, q = 0.f;
#pragma unroll
    for (int r = 0; r < BN_REP; r++) {
        s += g_z.bnsum[2][r][c];
        q += g_z.bnsum[2][r][128 + c];
    }
    float mean = s * (1.0f / (float)Nn);
    float var = q * (1.0f / (float)Nn) - mean * mean;
    float sc = gam[c] * rsqrtf(var + EPSf);
    float sh = bet[c] - mean * sc;

    int start = blockIdx.x * PCHUNK;
    if (start >= Nn) return;
    int end = min(start + PCHUNK, Nn);
    float acc = 0.f, ccnt = 0.f;
    int gp = batch[start];
    for (int n = start; n < end; n++) {
        int g = batch[n];
        if (g != gp) {
            atomicAdd(&g_z.xsum[gp * 128 + c], acc);
            if (c == 0) atomicAdd(&g_z.cnt[gp], ccnt);
            acc = 0.f; ccnt = 0.f; gp = g;
        }
        float a = __half2float(g_agg16[(size_t)n * 128 + c]);
        float v = fmaxf(fmaf(a, sc, sh), 0.f) + __half2float(g_act16[(size_t)n * 128 + c]);
        acc += v;
        ccnt += 1.f;
    }
    atomicAdd(&g_z.xsum[gp * 128 + c], acc);
    if (c == 0) atomicAdd(&g_z.cnt[gp], ccnt);
}

// ---------------- MLP head ----------------
__global__ void k_mlp(const float* __restrict__ Wm1, const float* __restrict__ bm1,
                      const float* __restrict__ Wm2, const float* __restrict__ bm2,
                      float* __restrict__ out) {
    __shared__ float zs[128], zm[128], hid[128];
    int g = blockIdx.x, c = threadIdx.x;
    float cnt = fmaxf(g_z.cnt[g], 1.0f);
    float xs = g_z.xsum[g * 128 + c];
    zs[c] = xs;
    zm[c] = xs / cnt;
    __syncthreads();
    float acc = bm1[c];
#pragma unroll 8
    for (int k = 0; k < 128; k++)
        acc += zs[k] * Wm1[k * 128 + c] + zm[k] * Wm1[(128 + k) * 128 + c];
    hid[c] = fmaxf(acc, 0.f) * Wm2[c];
    __syncthreads();
    for (int s = 64; s > 0; s >>= 1) {
        if (c < s) hid[c] += hid[c + s];
        __syncthreads();
    }
    if (c == 0) out[g] = hid[0] + bm2[0];
}

// ---------------- host ----------------
extern "C" void kernel_launch(void* const* d_in, const int* in_sizes, int n_in,
                              void* d_out, int out_size) {
    const float *x, *W1, *b1, *W2, *b2, *W3, *b3;
    const float *g1, *be1, *g2, *be2, *g3, *be3;
    const float *Wm1, *bm1, *Wm2, *bm2;
    const int *ei, *batch;

    if (in_sizes[1] == 2 * Ee) {
        x   = (const float*)d_in[0];
        ei  = (const int*)  d_in[1];
        batch = (const int*)d_in[2];
        W1 = (const float*)d_in[3];  b1 = (const float*)d_in[4];
        W2 = (const float*)d_in[5];  b2 = (const float*)d_in[6];
        W3 = (const float*)d_in[7];  b3 = (const float*)d_in[8];
        g1 = (const float*)d_in[9];  be1 = (const float*)d_in[10];
        g2 = (const float*)d_in[11]; be2 = (const float*)d_in[12];
        g3 = (const float*)d_in[13]; be3 = (const float*)d_in[14];
        Wm1 = (const float*)d_in[15]; bm1 = (const float*)d_in[16];
        Wm2 = (const float*)d_in[17]; bm2 = (const float*)d_in[18];
    } else {
        x   = (const float*)d_in[0];
        W1 = (const float*)d_in[1];  b1 = (const float*)d_in[2];
        g1 = (const float*)d_in[3];  be1 = (const float*)d_in[4];
        W2 = (const float*)d_in[5];  b2 = (const float*)d_in[6];
        g2 = (const float*)d_in[7];  be2 = (const float*)d_in[8];
        W3 = (const float*)d_in[9];  b3 = (const float*)d_in[10];
        g3 = (const float*)d_in[11]; be3 = (const float*)d_in[12];
        Wm1 = (const float*)d_in[13]; bm1 = (const float*)d_in[14];
        Wm2 = (const float*)d_in[15]; bm2 = (const float*)d_in[16];
        ei  = (const int*)d_in[17];
        batch = (const int*)d_in[18];
    }

    const int* src = ei;
    const int* dst = ei + Ee;
    float* out = (float*)d_out;

    static cudaStream_t s_side = nullptr;
    static cudaEvent_t s_e1 = nullptr, s_e2 = nullptr;
    if (!s_side) {
        cudaStreamCreateWithFlags(&s_side, cudaStreamNonBlocking);
        cudaEventCreateWithFlags(&s_e1, cudaEventDisableTiming);
        cudaEventCreateWithFlags(&s_e2, cudaEventDisableTiming);
    }

    cudaFuncSetAttribute(gemm_tc, cudaFuncAttributeMaxDynamicSharedMemorySize, SM_TOTAL);

    const int ZB = (Nn + 255) / 256;          // 391
    const int EB = (Ee + 255) / 256;          // 6250
    const int GATB = (Nn + 15) / 16;          // 6250 x 512
    const int POOLB = (Nn + PCHUNK - 1) / PCHUNK;  // 782

    void* zptr = nullptr;
    cudaGetSymbolAddress(&zptr, g_z);
    cudaMemsetAsync(zptr, 0, sizeof(ZBlob), 0);

    k_deg<<<EB, 256>>>(dst);
    cudaEventRecord(s_e1, 0);
    cudaStreamWaitEvent(s_side, s_e1, 0);

    k_prep<<<DINVB + 384, 128>>>(W1, W2, W3);
    k_scan1<<<NBLK, SCAN_BS, 0, s_side>>>();
    gemm_tc<<<TILES, 512, SM_TOTAL>>>(x, 0, 0, 0, nullptr, nullptr);
    k_scan2<<<1, 128, 0, s_side>>>();
    k_scan3<<<ZB, 256, 0, s_side>>>();
    k_fill<<<EB, 256, 0, s_side>>>(src, dst);
    cudaEventRecord(s_e2, s_side);
    cudaStreamWaitEvent(0, s_e2, 0);

    k_gather<<<GATB, 512>>>(b1, 0);

    gemm_tc<<<TILES, 512, SM_TOTAL>>>(nullptr, 1, 1, 0, g1, be1);
    k_gather<<<GATB, 512>>>(b2, 1);

    gemm_tc<<<TILES, 512, SM_TOTAL>>>(nullptr, 2, 2, 1, g2, be2);
    k_gather<<<GATB, 512>>>(b3, 2);

    k_pool<<<POOLB, 128>>>(batch, g3, be3);
    k_mlp<<<Gg, 128>>>(Wm1, bm1, Wm2, bm2, out);
}